// round 6
// baseline (speedup 1.0000x reference)
#include <cuda_runtime.h>
#include <cuda_bf16.h>
#include <cstdint>

typedef unsigned long long u64;
typedef unsigned int u32;

#define MARGIN 6.0f

// ---------------- device scratch (allocation-free rule) ----------------
__device__ __align__(16) float g_Wct[256 * 128];        // Wc^T [c][d]
__device__ __align__(16) float g_W2t[2 * 256 * 128];    // W2^T per layer [j][d] (rescue)
__device__ __align__(16) float g_G[256 * 128];          // cb + cb@Wz^T + bc
__device__ __align__(16) float g_V[2048 * 128];         // xhat @ Wx^T
__device__ __align__(16) __nv_bfloat16 g_W1b[2][32768]; // W1 bf16 [j=256][d=128] row-major
__device__ __align__(16) __nv_bfloat16 g_W2b[2][32768]; // W2 bf16 [d=128][h=256] row-major

// ---------------- PTX helpers ----------------
__device__ __forceinline__ u32 smem_u32(const void* p) {
    u32 a; asm("{ .reg .u64 t; cvta.to.shared.u64 t, %1; cvt.u32.u64 %0, t; }" : "=r"(a) : "l"(p));
    return a;
}
__device__ __forceinline__ void cp16(void* sd, const void* g) {
    u32 s = smem_u32(sd);
    asm volatile("cp.async.cg.shared.global [%0], [%1], 16;" :: "r"(s), "l"(g));
}
#define CP_COMMIT() asm volatile("cp.async.commit_group;")
#define CP_WAIT0()  asm volatile("cp.async.wait_group 0;")
#define CP_WAIT1()  asm volatile("cp.async.wait_group 1;")

__device__ __forceinline__ void ldsm4(u32& r0, u32& r1, u32& r2, u32& r3, u32 addr) {
    asm volatile("ldmatrix.sync.aligned.m8n8.x4.shared.b16 {%0,%1,%2,%3}, [%4];"
                 : "=r"(r0), "=r"(r1), "=r"(r2), "=r"(r3) : "r"(addr));
}
__device__ __forceinline__ void mma16816(float* c, u32 a0, u32 a1, u32 a2, u32 a3,
                                         u32 b0, u32 b1) {
    asm volatile("mma.sync.aligned.m16n8k16.row.col.f32.bf16.bf16.f32 "
                 "{%0,%1,%2,%3},{%4,%5,%6,%7},{%8,%9},{%0,%1,%2,%3};"
                 : "+f"(c[0]), "+f"(c[1]), "+f"(c[2]), "+f"(c[3])
                 : "r"(a0), "r"(a1), "r"(a2), "r"(a3), "r"(b0), "r"(b1));
}
__device__ __forceinline__ u32 pkbf2(float lo, float hi) {
    u32 r; asm("cvt.rn.bf16x2.f32 %0, %1, %2;" : "=r"(r) : "f"(hi), "f"(lo)); return r;
}

// ---------------- prep kernels ----------------
__global__ void k_wct(const float* __restrict__ Wc) {
    int c = blockIdx.x, d = threadIdx.x;
    g_Wct[c * 128 + d] = Wc[d * 256 + c];
}
__global__ void k_w2t(const float* __restrict__ W2_0, const float* __restrict__ W2_1) {
    int blk = blockIdx.x >> 8, j = blockIdx.x & 255, d = threadIdx.x;
    const float* W2 = blk ? W2_1 : W2_0;
    g_W2t[blk * 32768 + j * 128 + d] = W2[d * 256 + j];
}
__global__ void k_G(const float* __restrict__ cb, const float* __restrict__ bc) {
    int k = blockIdx.x, d = threadIdx.x;
    __shared__ float s[128];
    s[d] = cb[k * 128 + d];
    __syncthreads();
    float a = 0.f;
#pragma unroll 4
    for (int e = 0; e < 128; ++e) a = fmaf(s[e], g_Wct[e * 128 + d], a);
    g_G[k * 128 + d] = s[d] + a + bc[d];
}
__global__ void k_V(const float* __restrict__ xhat) {
    int b = blockIdx.x, d = threadIdx.x;
    __shared__ float s[128];
    s[d] = xhat[b * 128 + d];
    __syncthreads();
    float a = 0.f;
#pragma unroll 4
    for (int e = 0; e < 128; ++e) a = fmaf(s[e], g_Wct[(128 + e) * 128 + d], a);
    g_V[b * 128 + d] = a;
}
__global__ void k_wb(const float* __restrict__ W1_0, const float* __restrict__ W1_1,
                     const float* __restrict__ W2_0, const float* __restrict__ W2_1) {
    int idx = blockIdx.x * 256 + threadIdx.x;    // 131072
    int which = idx >> 16, lay = (idx >> 15) & 1, e = idx & 32767;
    if (which == 0) g_W1b[lay][e] = __float2bfloat16((lay ? W1_1 : W1_0)[e]);
    else            g_W2b[lay][e] = __float2bfloat16((lay ? W2_1 : W2_0)[e]);
}

// ---------------- smem map ----------------
#define SM_Z    0                  // 256 rows x 256B bf16, XOR-swizzled
#define SM_W1S  65536              // 2 x 16KB W1 slices (64 j-rows x 256B)
#define SM_W2S  98304              // 2 x 16KB W2 slices (128 d-rows x 128B)
#define SM_SU   131072
#define SM_DIST 131584
#define SM_RED  132608
#define SM_BC   132672
#define SM_CCNT 132676
#define SM_CAND 132680
#define SM_ZC   132736
#define SM_ZB   133248
#define SM_SH   133760
#define SMEMSZ  134784

// slice loaders: slice s -> (layer = s>>2, jc = s&3), buf = s&1
__device__ __forceinline__ void load_slice(unsigned char* sm, int s, int t) {
    int layer = s >> 2, jc = s & 3, buf = s & 1;
    const unsigned char* w1 = (const unsigned char*)g_W1b[layer];
    const unsigned char* w2 = (const unsigned char*)g_W2b[layer];
#pragma unroll
    for (int q = 0; q < 2; ++q) {          // W1: 64 rows x 16 chunks
        int i = t + q * 512;
        int r = i >> 4, c = i & 15;
        cp16(sm + SM_W1S + buf * 16384 + r * 256 + (((c ^ r) & 7) << 4) + ((c & 8) << 4),
             w1 + (jc * 64 + r) * 256 + c * 16);
    }
#pragma unroll
    for (int q = 0; q < 2; ++q) {          // W2: 128 rows x 8 chunks (k-cols jc*64..)
        int i = t + q * 512;
        int r = i >> 3, c = i & 7;
        cp16(sm + SM_W2S + buf * 16384 + r * 128 + ((c ^ (r & 7)) << 4),
             w2 + r * 512 + jc * 128 + c * 16);
    }
    CP_COMMIT();
}

// ---------------- main kernel ----------------
__global__ __launch_bounds__(512, 1) void k_main(const float* __restrict__ xhat,
                                                 const float* __restrict__ x,
                                                 const float* __restrict__ W1_0,
                                                 const float* __restrict__ W1_1,
                                                 float* __restrict__ out, int bs) {
    extern __shared__ __align__(1024) unsigned char sm[];
    const u32 smb = smem_u32(sm);
    const int t = threadIdx.x, wid = t >> 5, lane = t & 31, b = blockIdx.x;
    float* su = (float*)(sm + SM_SU);
    float* s_dist = (float*)(sm + SM_DIST);
    float* s_red = (float*)(sm + SM_RED);

    load_slice(sm, 0, t);
    load_slice(sm, 1, t);

    if (t < 128) su[t] = xhat[b * 128 + t] - x[b * 128 + t];
    if (t == 0) *(int*)(sm + SM_CCNT) = 0;

    // Z init: bf16(G + V) into swizzled smem
    // chunk c = cu>>2 ; offset = r*256 + ((c^r)&7)*16 + (c&8)*16 + (cu&3)*4
    {
        const float* Vb = g_V + b * 128;
#pragma unroll 4
        for (int i = 0; i < 32; ++i) {
            int idx = t + i * 512;
            int r = idx >> 6, cu = idx & 63;
            float2 g = *(const float2*)(g_G + r * 128 + cu * 2);
            float2 v = *(const float2*)(Vb + cu * 2);
            u32 p = pkbf2(g.x + v.x, g.y + v.y);
            *(u32*)(sm + SM_Z + r * 256 + ((((cu >> 2) ^ r) & 7) << 4)
                    + ((cu & 32) << 2) + (cu & 3) * 4) = p;
        }
    }

    const int m0 = wid * 16, gr = lane >> 2, gc2 = (lane & 3) * 2;
    const int jr7 = lane & 7, l2q = (lane >> 3) & 3;
    const int rowA = m0 + (lane & 15), hiA = lane >> 4;

    u32 za[8][4];
    for (int s = 0; s < 8; ++s) {
        CP_WAIT1();
        __syncthreads();
        const int buf = s & 1;
        if ((s & 3) == 0) {   // layer start: load Z A-fragments (16 rows x K=128)
#pragma unroll
            for (int kt = 0; kt < 8; ++kt) {
                int c = kt * 2 + hiA;
                u32 addr = smb + SM_Z + rowA * 256 + (((c ^ rowA) & 7) << 4) + ((c & 8) << 4);
                ldsm4(za[kt][0], za[kt][1], za[kt][2], za[kt][3], addr);
            }
        }
        // GEMM1: Hacc(16 rows x 64 hidden) = Z @ W1slice^T
        float Hacc[8][4];
#pragma unroll
        for (int nt = 0; nt < 8; ++nt)
#pragma unroll
            for (int e = 0; e < 4; ++e) Hacc[nt][e] = 0.f;
        const u32 w1b = smb + SM_W1S + buf * 16384;
#pragma unroll
        for (int ktp = 0; ktp < 4; ++ktp) {
#pragma unroll
            for (int nt = 0; nt < 8; ++nt) {
                int jrow = nt * 8 + jr7;
                int c = ktp * 4 + l2q;
                u32 b0, b1, b2, b3;
                ldsm4(b0, b1, b2, b3,
                      w1b + jrow * 256 + (((c ^ jrow) & 7) << 4) + ((c & 8) << 4));
                mma16816(Hacc[nt], za[2 * ktp][0], za[2 * ktp][1], za[2 * ktp][2], za[2 * ktp][3], b0, b1);
                mma16816(Hacc[nt], za[2 * ktp + 1][0], za[2 * ktp + 1][1], za[2 * ktp + 1][2], za[2 * ktp + 1][3], b2, b3);
            }
        }
        // relu + pack -> GEMM2 A-fragments (4 k16-chunks over the 64 hidden)
        u32 af[4][4];
#pragma unroll
        for (int kt = 0; kt < 4; ++kt) {
#pragma unroll
            for (int e = 0; e < 4; ++e) {
                Hacc[2 * kt][e] = fmaxf(Hacc[2 * kt][e], 0.f);
                Hacc[2 * kt + 1][e] = fmaxf(Hacc[2 * kt + 1][e], 0.f);
            }
            af[kt][0] = pkbf2(Hacc[2 * kt][0], Hacc[2 * kt][1]);
            af[kt][1] = pkbf2(Hacc[2 * kt][2], Hacc[2 * kt][3]);
            af[kt][2] = pkbf2(Hacc[2 * kt + 1][0], Hacc[2 * kt + 1][1]);
            af[kt][3] = pkbf2(Hacc[2 * kt + 1][2], Hacc[2 * kt + 1][3]);
        }
        // GEMM2: Z += relu(H) @ W2slice, in two 64-col groups with smem RMW
        const u32 w2b = smb + SM_W2S + buf * 16384;
#pragma unroll
        for (int ntg = 0; ntg < 2; ++ntg) {
            float zp[8][4];
#pragma unroll
            for (int nt = 0; nt < 8; ++nt)
#pragma unroll
                for (int e = 0; e < 4; ++e) zp[nt][e] = 0.f;
#pragma unroll
            for (int ktp = 0; ktp < 2; ++ktp) {
#pragma unroll
                for (int nt = 0; nt < 8; ++nt) {
                    int drow = ntg * 64 + nt * 8 + jr7;
                    int c = ktp * 4 + l2q;
                    u32 b0, b1, b2, b3;
                    ldsm4(b0, b1, b2, b3, w2b + drow * 128 + ((c ^ (drow & 7)) << 4));
                    mma16816(zp[nt], af[2 * ktp][0], af[2 * ktp][1], af[2 * ktp][2], af[2 * ktp][3], b0, b1);
                    mma16816(zp[nt], af[2 * ktp + 1][0], af[2 * ktp + 1][1], af[2 * ktp + 1][2], af[2 * ktp + 1][3], b2, b3);
                }
            }
#pragma unroll
            for (int nt = 0; nt < 8; ++nt) {     // RMW own fragment of Z
                int ch = ntg * 8 + nt;
                int r0 = m0 + gr, r1 = r0 + 8;
                u32* p0 = (u32*)(sm + SM_Z + r0 * 256 + (((ch ^ r0) & 7) << 4) + ((ch & 8) << 4) + gc2 * 2);
                u32* p1 = (u32*)(sm + SM_Z + r1 * 256 + (((ch ^ r1) & 7) << 4) + ((ch & 8) << 4) + gc2 * 2);
                float2 o0 = __bfloat1622float2(*(__nv_bfloat162*)p0);
                float2 o1 = __bfloat1622float2(*(__nv_bfloat162*)p1);
                *p0 = pkbf2(o0.x + zp[nt][0], o0.y + zp[nt][1]);
                *p1 = pkbf2(o1.x + zp[nt][2], o1.y + zp[nt][3]);
            }
        }
        __syncthreads();
        if (s < 6) load_slice(sm, s + 2, t);
    }
    __syncthreads();

    // ---------- distances from bf16 Z ----------
    if (t < 256) {
        float ds = 0.f;
#pragma unroll 8
        for (int cu = 0; cu < 64; ++cu) {
            u32 v = *(u32*)(sm + SM_Z + t * 256 + ((((cu >> 2) ^ t) & 7) << 4)
                            + ((cu & 32) << 2) + (cu & 3) * 4);
            float2 zf = __bfloat1622float2(*(__nv_bfloat162*)&v);
            float e0 = zf.x + su[2 * cu], e1 = zf.y + su[2 * cu + 1];
            ds = fmaf(e0, e0, fmaf(e1, e1, ds));
        }
        s_dist[t] = ds;
        float m = ds;
#pragma unroll
        for (int o = 16; o; o >>= 1) m = fminf(m, __shfl_xor_sync(~0u, m, o));
        if (lane == 0) s_red[wid] = m;
    }
    __syncthreads();
    if (t == 0) {
        float m = s_red[0];
#pragma unroll
        for (int w = 1; w < 8; ++w) m = fminf(m, s_red[w]);
        *(float*)(sm + SM_BC) = m;
    }
    __syncthreads();
    if (t < 256) {
        float dmin = *(float*)(sm + SM_BC);
        if (s_dist[t] <= dmin + MARGIN) {
            int pos = atomicAdd((int*)(sm + SM_CCNT), 1);
            if (pos < 8) ((int*)(sm + SM_CAND))[pos] = t;
        }
    }
    __syncthreads();

    // ---------- exact fp32 rescue ----------
    int ncand = *(int*)(sm + SM_CCNT);
    if (ncand > 8) ncand = 8;
    float* zc = (float*)(sm + SM_ZC);
    float* zb = (float*)(sm + SM_ZB);
    float* sh = (float*)(sm + SM_SH);
    u64 best = ~0ull;
    for (int c = 0; c < ncand; ++c) {
        int k = ((int*)(sm + SM_CAND))[c];
        if (t < 128) zc[t] = g_G[k * 128 + t] + g_V[b * 128 + t];
        __syncthreads();
        for (int L = 0; L < 2; ++L) {
            if (t < 256) {
                const float* wr = (L ? W1_1 : W1_0) + t * 128;
                float a = 0.f;
#pragma unroll 4
                for (int d = 0; d < 128; ++d) a = fmaf(zc[d], wr[d], a);
                sh[t] = fmaxf(a, 0.f);
            }
            __syncthreads();
            float upd = 0.f;
            if (t < 128) {
                const float* w2 = g_W2t + L * 32768 + t;
#pragma unroll 4
                for (int j = 0; j < 256; ++j) upd = fmaf(sh[j], w2[j * 128], upd);
            }
            __syncthreads();
            if (t < 128) zc[t] += upd;
            __syncthreads();
        }
        float p = 0.f;
        if (t < 128) { float e = zc[t] + su[t]; p = e * e; }
#pragma unroll
        for (int o = 16; o; o >>= 1) p += __shfl_xor_sync(~0u, p, o);
        if ((t & 31) == 0 && t < 128) s_red[t >> 5] = p;
        __syncthreads();
        if (t == 0)
            *(float*)(sm + SM_BC) = s_red[0] + s_red[1] + s_red[2] + s_red[3];
        __syncthreads();
        float dc = *(float*)(sm + SM_BC);
        u64 pk = ((u64)__float_as_uint(dc) << 32) | (u32)k;
        if (pk < best) {
            best = pk;
            if (t < 128) zb[t] = zc[t];
        }
        __syncthreads();
    }
    if (t == 0) out[b] = (float)(u32)(best & 0xffffffffu);
    if (t < 128) out[bs + b * 128 + t] = zb[t];
}

// ---------------- launch ----------------
extern "C" void kernel_launch(void* const* d_in, const int* in_sizes, int n_in,
                              void* d_out, int out_size) {
    const float* xhat = (const float*)d_in[0];
    const float* x    = (const float*)d_in[1];
    const float* cb   = (const float*)d_in[2];
    const float* Wc   = (const float*)d_in[3];
    const float* bc   = (const float*)d_in[4];
    const float* W1_0 = (const float*)d_in[5];
    const float* W2_0 = (const float*)d_in[6];
    const float* W1_1 = (const float*)d_in[7];
    const float* W2_1 = (const float*)d_in[8];
    float* out = (float*)d_out;
    const int bs = in_sizes[0] / 128;

    static bool attr = false;
    if (!attr) {
        cudaFuncSetAttribute(k_main, cudaFuncAttributeMaxDynamicSharedMemorySize, SMEMSZ);
        attr = true;
    }

    k_wct<<<256, 128>>>(Wc);
    k_w2t<<<512, 128>>>(W2_0, W2_1);
    k_wb<<<512, 256>>>(W1_0, W1_1, W2_0, W2_1);
    k_G<<<256, 128>>>(cb, bc);
    k_V<<<bs, 128>>>(xhat);
    k_main<<<bs, 512, SMEMSZ>>>(xhat, x, W1_0, W1_1, out, bs);
}

// round 8
// speedup vs baseline: 1.4451x; 1.4451x over previous
#include <cuda_runtime.h>
#include <cuda_bf16.h>
#include <cstdint>

typedef unsigned long long u64;
typedef unsigned int u32;

#define MARGIN 6.0f

// ---------------- device scratch (allocation-free rule) ----------------
__device__ __align__(16) float g_Wct[256 * 128];        // Wc^T [c][d]
__device__ __align__(16) float g_W1t[2][128 * 256];     // W1^T per layer [d][j] (rescue, coalesced)
__device__ __align__(16) float g_W2t[2 * 256 * 128];    // W2^T per layer [j][d] (rescue)
__device__ __align__(16) float g_G[256 * 128];          // cb + cb@Wz^T + bc
__device__ __align__(16) float g_V[2048 * 128];         // xhat @ Wx^T
__device__ __align__(16) float g_Q1[2048 * 256];        // W1_0 @ v[b]  (per-row hidden bias)
__device__ __align__(16) __nv_bfloat16 g_P1b[256 * 256];   // P1 = W1_0 @ G^T, [k][j] bf16
__device__ __align__(16) __nv_bfloat16 g_W1b[2][32768]; // W1 bf16 [j=256][d=128] row-major
__device__ __align__(16) __nv_bfloat16 g_W2b[2][32768]; // W2 bf16 [d=128][h=256] row-major

// ---------------- PTX helpers ----------------
__device__ __forceinline__ u32 smem_u32(const void* p) {
    u32 a; asm("{ .reg .u64 t; cvta.to.shared.u64 t, %1; cvt.u32.u64 %0, t; }" : "=r"(a) : "l"(p));
    return a;
}
__device__ __forceinline__ void cp16(void* sd, const void* g) {
    u32 s = smem_u32(sd);
    asm volatile("cp.async.cg.shared.global [%0], [%1], 16;" :: "r"(s), "l"(g));
}
#define CP_COMMIT() asm volatile("cp.async.commit_group;")
#define CP_WAIT1()  asm volatile("cp.async.wait_group 1;")

__device__ __forceinline__ void ldsm4(u32& r0, u32& r1, u32& r2, u32& r3, u32 addr) {
    asm volatile("ldmatrix.sync.aligned.m8n8.x4.shared.b16 {%0,%1,%2,%3}, [%4];"
                 : "=r"(r0), "=r"(r1), "=r"(r2), "=r"(r3) : "r"(addr));
}
__device__ __forceinline__ void mma16816(float* c, u32 a0, u32 a1, u32 a2, u32 a3,
                                         u32 b0, u32 b1) {
    asm volatile("mma.sync.aligned.m16n8k16.row.col.f32.bf16.bf16.f32 "
                 "{%0,%1,%2,%3},{%4,%5,%6,%7},{%8,%9},{%0,%1,%2,%3};"
                 : "+f"(c[0]), "+f"(c[1]), "+f"(c[2]), "+f"(c[3])
                 : "r"(a0), "r"(a1), "r"(a2), "r"(a3), "r"(b0), "r"(b1));
}
__device__ __forceinline__ u32 pkbf2(float lo, float hi) {
    u32 r; asm("cvt.rn.bf16x2.f32 %0, %1, %2;" : "=r"(r) : "f"(hi), "f"(lo)); return r;
}

// ---------------- prep kernels ----------------
__global__ void k_wct(const float* __restrict__ Wc) {
    int c = blockIdx.x, d = threadIdx.x;
    g_Wct[c * 128 + d] = Wc[d * 256 + c];
}
__global__ void k_w1t(const float* __restrict__ W1_0, const float* __restrict__ W1_1) {
    int lay = blockIdx.x >> 7, d = blockIdx.x & 127, j = threadIdx.x;
    g_W1t[lay][d * 256 + j] = (lay ? W1_1 : W1_0)[j * 128 + d];
}
__global__ void k_w2t(const float* __restrict__ W2_0, const float* __restrict__ W2_1) {
    int blk = blockIdx.x >> 8, j = blockIdx.x & 255, d = threadIdx.x;
    const float* W2 = blk ? W2_1 : W2_0;
    g_W2t[blk * 32768 + j * 128 + d] = W2[d * 256 + j];
}
__global__ void k_G(const float* __restrict__ cb, const float* __restrict__ bc) {
    int k = blockIdx.x, d = threadIdx.x;
    __shared__ float s[128];
    s[d] = cb[k * 128 + d];
    __syncthreads();
    float a = 0.f;
#pragma unroll 4
    for (int e = 0; e < 128; ++e) a = fmaf(s[e], g_Wct[e * 128 + d], a);
    g_G[k * 128 + d] = s[d] + a + bc[d];
}
__global__ void k_V(const float* __restrict__ xhat) {
    int b = blockIdx.x, d = threadIdx.x;
    __shared__ float s[128];
    s[d] = xhat[b * 128 + d];
    __syncthreads();
    float a = 0.f;
#pragma unroll 4
    for (int e = 0; e < 128; ++e) a = fmaf(s[e], g_Wct[(128 + e) * 128 + d], a);
    g_V[b * 128 + d] = a;
}
__global__ void k_p1() {              // P1[k][j] = sum_d G[k][d] * W1_0[j][d]
    int k = blockIdx.x, j = threadIdx.x;
    __shared__ float s[128];
    if (j < 128) s[j] = g_G[k * 128 + j];
    __syncthreads();
    float a = 0.f;
#pragma unroll 4
    for (int d = 0; d < 128; ++d) a = fmaf(s[d], g_W1t[0][d * 256 + j], a);
    g_P1b[k * 256 + j] = __float2bfloat16(a);
}
__global__ void k_q1() {              // Q1[b][j] = sum_d V[b][d] * W1_0[j][d]
    int b = blockIdx.x, j = threadIdx.x;
    __shared__ float s[128];
    if (j < 128) s[j] = g_V[b * 128 + j];
    __syncthreads();
    float a = 0.f;
#pragma unroll 4
    for (int d = 0; d < 128; ++d) a = fmaf(s[d], g_W1t[0][d * 256 + j], a);
    g_Q1[b * 256 + j] = a;
}
__global__ void k_wb(const float* __restrict__ W1_0, const float* __restrict__ W1_1,
                     const float* __restrict__ W2_0, const float* __restrict__ W2_1) {
    int idx = blockIdx.x * 256 + threadIdx.x;    // 131072
    int which = idx >> 16, lay = (idx >> 15) & 1, e = idx & 32767;
    if (which == 0) g_W1b[lay][e] = __float2bfloat16((lay ? W1_1 : W1_0)[e]);
    else            g_W2b[lay][e] = __float2bfloat16((lay ? W2_1 : W2_0)[e]);
}

// ---------------- smem map ----------------
#define SM_Z    0                   // 256 rows x 256B bf16, XOR-swizzled
#define SM_WA   65536               // 2 x 32KB: layer0 = P1 slice (256r x 128B), layer1 = W1 slice
#define SM_WB   131072              // 2 x 16KB W2 slices (128 d-rows x 128B)
#define SM_Q1   163840              // 256 f32
#define SM_SU   164864
#define SM_DIST 165376
#define SM_RED  166400
#define SM_BC   166464
#define SM_CCNT 166468
#define SM_CAND 166472              // int[16]
#define SM_ZC   166592
#define SM_ZB   167104
#define SM_SH   167616
#define SMEMSZ  168640

// slice s: 0-3 layer0 (P1 slice + W2_0 slice), 4-7 layer1 (W1_1 + W2_1); buf = s&1
__device__ __forceinline__ void load_slice(unsigned char* sm, int s, int t) {
    int buf = s & 1, jc = s & 3;
    if (s < 4) {
        const unsigned char* p1 = (const unsigned char*)g_P1b;   // [256][256] bf16, 512B rows
        const unsigned char* w2 = (const unsigned char*)g_W2b[0];
#pragma unroll
        for (int q = 0; q < 4; ++q) {       // P1 slice: 256 rows x 8 chunks (128B rows)
            int i = t + q * 512;
            int r = i >> 3, c = i & 7;
            cp16(sm + SM_WA + buf * 32768 + r * 128 + (((c ^ r) & 7) << 4),
                 p1 + r * 512 + jc * 128 + c * 16);
        }
#pragma unroll
        for (int q = 0; q < 2; ++q) {       // W2_0 slice: 128 rows x 8 chunks
            int i = t + q * 512;
            int r = i >> 3, c = i & 7;
            cp16(sm + SM_WB + buf * 16384 + r * 128 + (((c ^ r) & 7) << 4),
                 w2 + r * 512 + jc * 128 + c * 16);
        }
    } else {
        const unsigned char* w1 = (const unsigned char*)g_W1b[1];
        const unsigned char* w2 = (const unsigned char*)g_W2b[1];
#pragma unroll
        for (int q = 0; q < 2; ++q) {       // W1_1 slice: 64 rows x 16 chunks (256B rows)
            int i = t + q * 512;
            int r = i >> 4, c = i & 15;
            cp16(sm + SM_WA + buf * 32768 + r * 256 + (((c ^ r) & 7) << 4) + ((c & 8) << 4),
                 w1 + (jc * 64 + r) * 256 + c * 16);
        }
#pragma unroll
        for (int q = 0; q < 2; ++q) {       // W2_1 slice
            int i = t + q * 512;
            int r = i >> 3, c = i & 7;
            cp16(sm + SM_WB + buf * 16384 + r * 128 + (((c ^ r) & 7) << 4),
                 w2 + r * 512 + jc * 128 + c * 16);
        }
    }
    CP_COMMIT();
}

// ---------------- main kernel ----------------
__global__ __launch_bounds__(512, 1) void k_main(const float* __restrict__ xhat,
                                                 const float* __restrict__ x,
                                                 float* __restrict__ out, int bs) {
    extern __shared__ __align__(1024) unsigned char sm[];
    const u32 smb = smem_u32(sm);
    const int t = threadIdx.x, wid = t >> 5, lane = t & 31, b = blockIdx.x;
    float* su = (float*)(sm + SM_SU);
    float* q1s = (float*)(sm + SM_Q1);
    float* s_dist = (float*)(sm + SM_DIST);
    float* s_red = (float*)(sm + SM_RED);

    load_slice(sm, 0, t);
    load_slice(sm, 1, t);

    if (t < 128) su[t] = xhat[b * 128 + t] - x[b * 128 + t];
    if (t == 0) *(int*)(sm + SM_CCNT) = 0;
    if (t < 256) q1s[t] = g_Q1[b * 256 + t];

    // Z init: bf16(G + V) into swizzled smem
    {
        const float* Vb = g_V + b * 128;
#pragma unroll 4
        for (int i = 0; i < 32; ++i) {
            int idx = t + i * 512;
            int r = idx >> 6, cu = idx & 63;
            float2 g = *(const float2*)(g_G + r * 128 + cu * 2);
            float2 v = *(const float2*)(Vb + cu * 2);
            u32 p = pkbf2(g.x + v.x, g.y + v.y);
            *(u32*)(sm + SM_Z + r * 256 + ((((cu >> 2) ^ r) & 7) << 4)
                    + ((cu & 32) << 2) + (cu & 3) * 4) = p;
        }
    }

    const int m0 = wid * 16, gr = lane >> 2, gc2 = (lane & 3) * 2;
    const int jr7 = lane & 7, l2q = (lane >> 3) & 3;
    const int rowA = m0 + (lane & 15), hiA = lane >> 4;
    const int fr0 = m0 + gr, fr1 = fr0 + 8;

    u32 za[8][4];
    for (int s = 0; s < 8; ++s) {
        CP_WAIT1();
        __syncthreads();
        const int buf = s & 1;
        float Hacc[8][4];
        if (s < 4) {
            // layer 0: H fragments = P1slice + q1 (no GEMM1) — LDS via generic pointer
            const unsigned char* pb = sm + SM_WA + buf * 32768;
#pragma unroll
            for (int nt = 0; nt < 8; ++nt) {
                int col = nt * 8 + gc2;
                float2 q = *(const float2*)(q1s + (s * 64 + col));
                u32 v0 = *(const u32*)(pb + fr0 * 128 + (((nt ^ fr0) & 7) << 4) + gc2 * 2);
                u32 v1 = *(const u32*)(pb + fr1 * 128 + (((nt ^ fr1) & 7) << 4) + gc2 * 2);
                float2 f0 = __bfloat1622float2(*(__nv_bfloat162*)&v0);
                float2 f1 = __bfloat1622float2(*(__nv_bfloat162*)&v1);
                Hacc[nt][0] = f0.x + q.x; Hacc[nt][1] = f0.y + q.y;
                Hacc[nt][2] = f1.x + q.x; Hacc[nt][3] = f1.y + q.y;
            }
        } else {
            if (s == 4) {   // layer 1 start: load Z A-fragments (16 rows x K=128)
#pragma unroll
                for (int kt = 0; kt < 8; ++kt) {
                    int c = kt * 2 + hiA;
                    u32 addr = smb + SM_Z + rowA * 256 + (((c ^ rowA) & 7) << 4) + ((c & 8) << 4);
                    ldsm4(za[kt][0], za[kt][1], za[kt][2], za[kt][3], addr);
                }
            }
#pragma unroll
            for (int nt = 0; nt < 8; ++nt)
#pragma unroll
                for (int e = 0; e < 4; ++e) Hacc[nt][e] = 0.f;
            const u32 w1b = smb + SM_WA + buf * 32768;
#pragma unroll
            for (int ktp = 0; ktp < 4; ++ktp) {
#pragma unroll
                for (int nt = 0; nt < 8; ++nt) {
                    int jrow = nt * 8 + jr7;
                    int c = ktp * 4 + l2q;
                    u32 b0, b1, b2, b3;
                    ldsm4(b0, b1, b2, b3,
                          w1b + jrow * 256 + (((c ^ jrow) & 7) << 4) + ((c & 8) << 4));
                    mma16816(Hacc[nt], za[2 * ktp][0], za[2 * ktp][1], za[2 * ktp][2], za[2 * ktp][3], b0, b1);
                    mma16816(Hacc[nt], za[2 * ktp + 1][0], za[2 * ktp + 1][1], za[2 * ktp + 1][2], za[2 * ktp + 1][3], b2, b3);
                }
            }
        }
        // relu + pack -> GEMM2 A-fragments
        u32 af[4][4];
#pragma unroll
        for (int kt = 0; kt < 4; ++kt) {
#pragma unroll
            for (int e = 0; e < 4; ++e) {
                Hacc[2 * kt][e] = fmaxf(Hacc[2 * kt][e], 0.f);
                Hacc[2 * kt + 1][e] = fmaxf(Hacc[2 * kt + 1][e], 0.f);
            }
            af[kt][0] = pkbf2(Hacc[2 * kt][0], Hacc[2 * kt][1]);
            af[kt][1] = pkbf2(Hacc[2 * kt][2], Hacc[2 * kt][3]);
            af[kt][2] = pkbf2(Hacc[2 * kt + 1][0], Hacc[2 * kt + 1][1]);
            af[kt][3] = pkbf2(Hacc[2 * kt + 1][2], Hacc[2 * kt + 1][3]);
        }
        // GEMM2: Z += relu(H) @ W2slice, two 64-col groups, smem RMW
        const u32 w2b = smb + SM_WB + buf * 16384;
#pragma unroll
        for (int ntg = 0; ntg < 2; ++ntg) {
            float zp[8][4];
#pragma unroll
            for (int nt = 0; nt < 8; ++nt)
#pragma unroll
                for (int e = 0; e < 4; ++e) zp[nt][e] = 0.f;
#pragma unroll
            for (int ktp = 0; ktp < 2; ++ktp) {
#pragma unroll
                for (int nt = 0; nt < 8; ++nt) {
                    int drow = ntg * 64 + nt * 8 + jr7;
                    int c = ktp * 4 + l2q;
                    u32 b0, b1, b2, b3;
                    ldsm4(b0, b1, b2, b3, w2b + drow * 128 + ((c ^ (drow & 7)) << 4));
                    mma16816(zp[nt], af[2 * ktp][0], af[2 * ktp][1], af[2 * ktp][2], af[2 * ktp][3], b0, b1);
                    mma16816(zp[nt], af[2 * ktp + 1][0], af[2 * ktp + 1][1], af[2 * ktp + 1][2], af[2 * ktp + 1][3], b2, b3);
                }
            }
#pragma unroll
            for (int nt = 0; nt < 8; ++nt) {
                int ch = ntg * 8 + nt;
                u32* p0 = (u32*)(sm + SM_Z + fr0 * 256 + (((ch ^ fr0) & 7) << 4) + ((ch & 8) << 4) + gc2 * 2);
                u32* p1 = (u32*)(sm + SM_Z + fr1 * 256 + (((ch ^ fr1) & 7) << 4) + ((ch & 8) << 4) + gc2 * 2);
                float2 o0 = __bfloat1622float2(*(__nv_bfloat162*)p0);
                float2 o1 = __bfloat1622float2(*(__nv_bfloat162*)p1);
                *p0 = pkbf2(o0.x + zp[nt][0], o0.y + zp[nt][1]);
                *p1 = pkbf2(o1.x + zp[nt][2], o1.y + zp[nt][3]);
            }
        }
        __syncthreads();
        if (s < 6) load_slice(sm, s + 2, t);
    }
    __syncthreads();

    // ---------- approx distances from bf16 Z ----------
    if (t < 256) {
        float ds = 0.f;
#pragma unroll 8
        for (int cu = 0; cu < 64; ++cu) {
            u32 v = *(u32*)(sm + SM_Z + t * 256 + ((((cu >> 2) ^ t) & 7) << 4)
                            + ((cu & 32) << 2) + (cu & 3) * 4);
            float2 zf = __bfloat1622float2(*(__nv_bfloat162*)&v);
            float e0 = zf.x + su[2 * cu], e1 = zf.y + su[2 * cu + 1];
            ds = fmaf(e0, e0, fmaf(e1, e1, ds));
        }
        s_dist[t] = ds;
        float m = ds;
#pragma unroll
        for (int o = 16; o; o >>= 1) m = fminf(m, __shfl_xor_sync(~0u, m, o));
        if (lane == 0) s_red[wid] = m;
    }
    __syncthreads();
    if (t == 0) {
        float m = s_red[0];
#pragma unroll
        for (int w = 1; w < 8; ++w) m = fminf(m, s_red[w]);
        *(float*)(sm + SM_BC) = m;
    }
    __syncthreads();
    if (t < 256) {
        float dmin = *(float*)(sm + SM_BC);
        if (s_dist[t] <= dmin + MARGIN) {
            int pos = atomicAdd((int*)(sm + SM_CCNT), 1);
            if (pos < 16) ((int*)(sm + SM_CAND))[pos] = t;
        }
    }
    __syncthreads();

    // ---------- exact fp32 rescue (coalesced via g_W1t / g_W2t) ----------
    int ncand = *(int*)(sm + SM_CCNT);
    if (ncand > 16) ncand = 16;
    float* zc = (float*)(sm + SM_ZC);
    float* zb = (float*)(sm + SM_ZB);
    float* sh = (float*)(sm + SM_SH);
    u64 best = ~0ull;
    for (int c = 0; c < ncand; ++c) {
        int k = ((int*)(sm + SM_CAND))[c];
        if (t < 128) zc[t] = g_G[k * 128 + t] + g_V[b * 128 + t];
        __syncthreads();
        for (int L = 0; L < 2; ++L) {
            if (t < 256) {
                const float* wt = g_W1t[L] + t;
                float a = 0.f;
#pragma unroll 4
                for (int d = 0; d < 128; ++d) a = fmaf(zc[d], wt[d * 256], a);
                sh[t] = fmaxf(a, 0.f);
            }
            __syncthreads();
            float upd = 0.f;
            if (t < 128) {
                const float* w2 = g_W2t + L * 32768 + t;
#pragma unroll 4
                for (int j = 0; j < 256; ++j) upd = fmaf(sh[j], w2[j * 128], upd);
            }
            __syncthreads();
            if (t < 128) zc[t] += upd;
            __syncthreads();
        }
        float p = 0.f;
        if (t < 128) { float e = zc[t] + su[t]; p = e * e; }
#pragma unroll
        for (int o = 16; o; o >>= 1) p += __shfl_xor_sync(~0u, p, o);
        if ((t & 31) == 0 && t < 128) s_red[t >> 5] = p;
        __syncthreads();
        if (t == 0)
            *(float*)(sm + SM_BC) = s_red[0] + s_red[1] + s_red[2] + s_red[3];
        __syncthreads();
        float dc = *(float*)(sm + SM_BC);
        u64 pk = ((u64)__float_as_uint(dc) << 32) | (u32)k;
        if (pk < best) {
            best = pk;
            if (t < 128) zb[t] = zc[t];
        }
        __syncthreads();
    }
    if (t == 0) out[b] = (float)(u32)(best & 0xffffffffu);
    if (t < 128) out[bs + b * 128 + t] = zb[t];
}

// ---------------- launch ----------------
extern "C" void kernel_launch(void* const* d_in, const int* in_sizes, int n_in,
                              void* d_out, int out_size) {
    const float* xhat = (const float*)d_in[0];
    const float* x    = (const float*)d_in[1];
    const float* cb   = (const float*)d_in[2];
    const float* Wc   = (const float*)d_in[3];
    const float* bc   = (const float*)d_in[4];
    const float* W1_0 = (const float*)d_in[5];
    const float* W2_0 = (const float*)d_in[6];
    const float* W1_1 = (const float*)d_in[7];
    const float* W2_1 = (const float*)d_in[8];
    float* out = (float*)d_out;
    const int bs = in_sizes[0] / 128;

    static bool attr = false;
    if (!attr) {
        cudaFuncSetAttribute(k_main, cudaFuncAttributeMaxDynamicSharedMemorySize, SMEMSZ);
        attr = true;
    }

    k_wct<<<256, 128>>>(Wc);
    k_w1t<<<256, 256>>>(W1_0, W1_1);
    k_w2t<<<512, 128>>>(W2_0, W2_1);
    k_wb<<<512, 256>>>(W1_0, W1_1, W2_0, W2_1);
    k_G<<<256, 128>>>(cb, bc);
    k_V<<<bs, 128>>>(xhat);
    k_p1<<<256, 256>>>();
    k_q1<<<bs, 256>>>();
    k_main<<<bs, 512, SMEMSZ>>>(xhat, x, out, bs);
}

// round 9
// speedup vs baseline: 1.9589x; 1.3556x over previous
#include <cuda_runtime.h>
#include <cuda_bf16.h>
#include <cstdint>

typedef unsigned long long u64;
typedef unsigned int u32;

#define MARGIN 6.0f

// ---------------- device scratch ----------------
__device__ __align__(16) float g_Wct[256 * 128];        // Wc^T [c][d]
__device__ __align__(16) float g_W1t[2][128 * 256];     // W1^T [d][j]
__device__ __align__(16) float g_W2t[2 * 256 * 128];    // W2^T [j][d]
__device__ __align__(16) float g_G[256 * 128];
__device__ __align__(16) float g_V[2048 * 128];
__device__ __align__(16) float g_Q1[2048 * 256];
__device__ __align__(16) __nv_bfloat16 g_P1b[256 * 256];
__device__ __align__(16) __nv_bfloat16 g_W1b[2][32768];
__device__ __align__(16) __nv_bfloat16 g_W2b[2][32768];

// ---------------- PTX helpers ----------------
__device__ __forceinline__ u32 smem_u32(const void* p) {
    u32 a; asm("{ .reg .u64 t; cvta.to.shared.u64 t, %1; cvt.u32.u64 %0, t; }" : "=r"(a) : "l"(p));
    return a;
}
__device__ __forceinline__ void cp16(void* sd, const void* g) {
    u32 s = smem_u32(sd);
    asm volatile("cp.async.cg.shared.global [%0], [%1], 16;" :: "r"(s), "l"(g));
}
#define CP_COMMIT() asm volatile("cp.async.commit_group;")
#define CP_WAIT1()  asm volatile("cp.async.wait_group 1;")

__device__ __forceinline__ void ldsm4(u32& r0, u32& r1, u32& r2, u32& r3, u32 addr) {
    asm volatile("ldmatrix.sync.aligned.m8n8.x4.shared.b16 {%0,%1,%2,%3}, [%4];"
                 : "=r"(r0), "=r"(r1), "=r"(r2), "=r"(r3) : "r"(addr));
}
__device__ __forceinline__ void mma16816(float* c, u32 a0, u32 a1, u32 a2, u32 a3,
                                         u32 b0, u32 b1) {
    asm volatile("mma.sync.aligned.m16n8k16.row.col.f32.bf16.bf16.f32 "
                 "{%0,%1,%2,%3},{%4,%5,%6,%7},{%8,%9},{%0,%1,%2,%3};"
                 : "+f"(c[0]), "+f"(c[1]), "+f"(c[2]), "+f"(c[3])
                 : "r"(a0), "r"(a1), "r"(a2), "r"(a3), "r"(b0), "r"(b1));
}
__device__ __forceinline__ u32 pkbf2(float lo, float hi) {
    u32 r; asm("cvt.rn.bf16x2.f32 %0, %1, %2;" : "=r"(r) : "f"(hi), "f"(lo)); return r;
}

// ---------------- fused prep kernels (3-launch plan) ----------------
__global__ void p_weights(const float* __restrict__ Wc,
                          const float* __restrict__ W1_0, const float* __restrict__ W1_1,
                          const float* __restrict__ W2_0, const float* __restrict__ W2_1) {
    int idx = blockIdx.x * 256 + threadIdx.x;             // 294912 total
    if (idx < 32768) {                                    // Wc^T
        int c = idx >> 7, d = idx & 127;
        g_Wct[c * 128 + d] = Wc[d * 256 + c];
    } else if (idx < 98304) {                             // W1^T
        int e = idx - 32768, lay = e >> 15, r = e & 32767;
        int d = r >> 8, j = r & 255;
        g_W1t[lay][d * 256 + j] = (lay ? W1_1 : W1_0)[j * 128 + d];
    } else if (idx < 163840) {                            // W2^T
        int e = idx - 98304, lay = e >> 15, r = e & 32767;
        int j = r >> 7, d = r & 127;
        g_W2t[lay * 32768 + j * 128 + d] = (lay ? W2_1 : W2_0)[d * 256 + j];
    } else {                                              // bf16 copies
        int e = idx - 163840;                             // 131072
        int which = e >> 16, lay = (e >> 15) & 1, q = e & 32767;
        if (which == 0) g_W1b[lay][q] = __float2bfloat16((lay ? W1_1 : W1_0)[q]);
        else            g_W2b[lay][q] = __float2bfloat16((lay ? W2_1 : W2_0)[q]);
    }
}
// blocks 0..255: G[k] + P1[k]; blocks 256..2303: V[b] + Q1[b]
__global__ void p_gvpq(const float* __restrict__ cb, const float* __restrict__ bc,
                       const float* __restrict__ xhat) {
    __shared__ float s[128], sr[128];
    int t = threadIdx.x;
    if (blockIdx.x < 256) {
        int k = blockIdx.x;
        if (t < 128) s[t] = cb[k * 128 + t];
        __syncthreads();
        if (t < 128) {
            float a = 0.f;
#pragma unroll 4
            for (int e = 0; e < 128; ++e) a = fmaf(s[e], g_Wct[e * 128 + t], a);
            float g = s[t] + a + bc[t];
            g_G[k * 128 + t] = g;
            sr[t] = g;
        }
        __syncthreads();
        float a = 0.f;
#pragma unroll 4
        for (int d = 0; d < 128; ++d) a = fmaf(sr[d], g_W1t[0][d * 256 + t], a);
        g_P1b[k * 256 + t] = __float2bfloat16(a);
    } else {
        int b = blockIdx.x - 256;
        if (t < 128) s[t] = xhat[b * 128 + t];
        __syncthreads();
        if (t < 128) {
            float a = 0.f;
#pragma unroll 4
            for (int e = 0; e < 128; ++e) a = fmaf(s[e], g_Wct[(128 + e) * 128 + t], a);
            g_V[b * 128 + t] = a;
            sr[t] = a;
        }
        __syncthreads();
        float a = 0.f;
#pragma unroll 4
        for (int d = 0; d < 128; ++d) a = fmaf(sr[d], g_W1t[0][d * 256 + t], a);
        g_Q1[b * 256 + t] = a;
    }
}

// ---------------- smem map ----------------
#define SM_Z    0                   // 256 rows x 256B bf16, XOR-swizzled
#define SM_WA   65536               // 2 x 8KB: P1 slice (128r x 64B packed) / W1 slice (32r x 256B)
#define SM_WB   81920               // 2 x 8KB: W2 slice (128r x 64B packed)
#define SM_Q1   98304               // 256 f32
#define SM_SU   99328
#define SM_DIST 99840
#define SM_RED  100864
#define SM_BC   100928
#define SM_CCNT 100932
#define SM_CAND 100936              // int[16]
#define SM_ZC   101024
#define SM_ZB   101536
#define SM_SH   102048
#define SMEMSZ  103072

// pair-packed 64B-row layout for P1/W2 slices (128 rows x 4 chunks):
// addr(r,c) = (r>>1)*128 + (r&1)*64 + ((c ^ ((r>>1)&3)) << 4)   [conflict-free]
__device__ __forceinline__ u32 pk64(int r, int c) {
    return (u32)((r >> 1) * 128 + (r & 1) * 64 + ((c ^ ((r >> 1) & 3)) << 4));
}

// ring step i: 0-15 layer0 (rg = i>>3, jc = i&7): P1 slice + W2_0 slice
//              16-23 layer1 (jc = i-16): W1_1 slice + W2_1 slice.  buf = i&1
__device__ __forceinline__ void load_step(unsigned char* sm, int i, int t) {
    int buf = i & 1;
    if (i < 16) {
        int rg = i >> 3, jc = i & 7;
        const unsigned char* p1 = (const unsigned char*)g_P1b;   // [256][256] bf16
        const unsigned char* w2 = (const unsigned char*)g_W2b[0];
#pragma unroll
        for (int q = 0; q < 2; ++q) {       // P1: 128 rows x 4 chunks (this rg's rows)
            int e = t + q * 256;
            int r = e >> 2, c = e & 3;
            cp16(sm + SM_WA + buf * 8192 + pk64(r, c),
                 p1 + (rg * 128 + r) * 512 + jc * 64 + c * 16);
        }
#pragma unroll
        for (int q = 0; q < 2; ++q) {       // W2_0: 128 rows x 4 chunks
            int e = t + q * 256;
            int r = e >> 2, c = e & 3;
            cp16(sm + SM_WB + buf * 8192 + pk64(r, c),
                 w2 + r * 512 + jc * 64 + c * 16);
        }
    } else {
        int jc = i - 16;
        const unsigned char* w1 = (const unsigned char*)g_W1b[1];
        const unsigned char* w2 = (const unsigned char*)g_W2b[1];
#pragma unroll
        for (int q = 0; q < 2; ++q) {       // W1_1: 32 rows x 16 chunks (256B rows)
            int e = t + q * 256;
            int r = e >> 4, c = e & 15;
            cp16(sm + SM_WA + buf * 8192 + r * 256 + (((c ^ r) & 7) << 4) + ((c & 8) << 4),
                 w1 + (jc * 32 + r) * 256 + c * 16);
        }
#pragma unroll
        for (int q = 0; q < 2; ++q) {       // W2_1: 128 rows x 4 chunks
            int e = t + q * 256;
            int r = e >> 2, c = e & 3;
            cp16(sm + SM_WB + buf * 8192 + pk64(r, c),
                 w2 + r * 512 + jc * 64 + c * 16);
        }
    }
    CP_COMMIT();
}

// GEMM2 (K=32) + Z RMW for one row-group. af[2][4] = relu'd H k-chunks.
__device__ __forceinline__ void gemm2_rmw(unsigned char* sm, u32 smb, int buf,
                                          const u32 af[2][4], int fr0, int fr1,
                                          int jr7, int l2q, int gc2) {
    const u32 w2b = smb + SM_WB + buf * 8192;
#pragma unroll
    for (int ntg = 0; ntg < 2; ++ntg) {
        float zp[8][4];
#pragma unroll
        for (int nt = 0; nt < 8; ++nt)
#pragma unroll
            for (int e = 0; e < 4; ++e) zp[nt][e] = 0.f;
#pragma unroll
        for (int nt = 0; nt < 8; ++nt) {
            int drow = ntg * 64 + nt * 8 + jr7;
            u32 b0, b1, b2, b3;
            ldsm4(b0, b1, b2, b3, w2b + pk64(drow, l2q));
            mma16816(zp[nt], af[0][0], af[0][1], af[0][2], af[0][3], b0, b1);
            mma16816(zp[nt], af[1][0], af[1][1], af[1][2], af[1][3], b2, b3);
        }
#pragma unroll
        for (int nt = 0; nt < 8; ++nt) {
            int ch = ntg * 8 + nt;
            u32* p0 = (u32*)(sm + SM_Z + fr0 * 256 + (((ch ^ fr0) & 7) << 4) + ((ch & 8) << 4) + gc2 * 2);
            u32* p1 = (u32*)(sm + SM_Z + fr1 * 256 + (((ch ^ fr1) & 7) << 4) + ((ch & 8) << 4) + gc2 * 2);
            float2 o0 = __bfloat1622float2(*(__nv_bfloat162*)p0);
            float2 o1 = __bfloat1622float2(*(__nv_bfloat162*)p1);
            *p0 = pkbf2(o0.x + zp[nt][0], o0.y + zp[nt][1]);
            *p1 = pkbf2(o1.x + zp[nt][2], o1.y + zp[nt][3]);
        }
    }
}

// ---------------- main kernel: 256 threads, 2 row-groups/warp, 2 CTA/SM ----------------
__global__ __launch_bounds__(256, 2) void k_main(const float* __restrict__ xhat,
                                                 const float* __restrict__ x,
                                                 float* __restrict__ out, int bs) {
    extern __shared__ __align__(1024) unsigned char sm[];
    const u32 smb = smem_u32(sm);
    const int t = threadIdx.x, wid = t >> 5, lane = t & 31, b = blockIdx.x;
    float* su = (float*)(sm + SM_SU);
    float* q1s = (float*)(sm + SM_Q1);
    float* s_dist = (float*)(sm + SM_DIST);
    float* s_red = (float*)(sm + SM_RED);

    load_step(sm, 0, t);
    load_step(sm, 1, t);

    if (t < 128) su[t] = xhat[b * 128 + t] - x[b * 128 + t];
    if (t == 0) *(int*)(sm + SM_CCNT) = 0;
    q1s[t] = g_Q1[b * 256 + t];

    // Z init: bf16(G + V), swizzled
    {
        const float* Vb = g_V + b * 128;
#pragma unroll 4
        for (int i = 0; i < 64; ++i) {
            int idx = t + i * 256;
            int r = idx >> 6, cu = idx & 63;
            float2 g = *(const float2*)(g_G + r * 128 + cu * 2);
            float2 v = *(const float2*)(Vb + cu * 2);
            u32 p = pkbf2(g.x + v.x, g.y + v.y);
            *(u32*)(sm + SM_Z + r * 256 + ((((cu >> 2) ^ r) & 7) << 4)
                    + ((cu & 32) << 2) + (cu & 3) * 4) = p;
        }
    }

    const int gr = lane >> 2, gc2 = (lane & 3) * 2;
    const int jr7 = lane & 7, l2q = (lane >> 3) & 3;
    const int hiA = lane >> 4;

    for (int i = 0; i < 24; ++i) {
        CP_WAIT1();
        __syncthreads();
        const int buf = i & 1;
        if (i < 16) {
            // ---- layer 0, one row-group per step ----
            const int rg = i >> 3;
            const int m0 = wid * 16 + rg * 128;
            const int fr0 = m0 + gr, fr1 = fr0 + 8;
            const int lr0 = wid * 16 + gr, lr1 = lr0 + 8;   // row within P1 slice
            const unsigned char* pb = sm + SM_WA + buf * 8192;
            float Hacc[4][4];
#pragma unroll
            for (int nt = 0; nt < 4; ++nt) {
                int ncol = nt * 8 + gc2;
                float2 q = *(const float2*)(q1s + ((i & 7) * 32 + ncol));
                int cc = ncol >> 3, ib = (ncol & 7) * 2;
                u32 v0 = *(const u32*)(pb + pk64(lr0, cc) + ib);
                u32 v1 = *(const u32*)(pb + pk64(lr1, cc) + ib);
                float2 f0 = __bfloat1622float2(*(__nv_bfloat162*)&v0);
                float2 f1 = __bfloat1622float2(*(__nv_bfloat162*)&v1);
                Hacc[nt][0] = f0.x + q.x; Hacc[nt][1] = f0.y + q.y;
                Hacc[nt][2] = f1.x + q.x; Hacc[nt][3] = f1.y + q.y;
            }
            u32 af[2][4];
#pragma unroll
            for (int kt = 0; kt < 2; ++kt) {
#pragma unroll
                for (int e = 0; e < 4; ++e) {
                    Hacc[2 * kt][e] = fmaxf(Hacc[2 * kt][e], 0.f);
                    Hacc[2 * kt + 1][e] = fmaxf(Hacc[2 * kt + 1][e], 0.f);
                }
                af[kt][0] = pkbf2(Hacc[2 * kt][0], Hacc[2 * kt][1]);
                af[kt][1] = pkbf2(Hacc[2 * kt][2], Hacc[2 * kt][3]);
                af[kt][2] = pkbf2(Hacc[2 * kt + 1][0], Hacc[2 * kt + 1][1]);
                af[kt][3] = pkbf2(Hacc[2 * kt + 1][2], Hacc[2 * kt + 1][3]);
            }
            gemm2_rmw(sm, smb, buf, af, fr0, fr1, jr7, l2q, gc2);
        } else {
            // ---- layer 1, both row-groups ----
#pragma unroll 1
            for (int rg = 0; rg < 2; ++rg) {
                const int m0 = wid * 16 + rg * 128;
                const int fr0 = m0 + gr, fr1 = fr0 + 8;
                const int rowA = m0 + (lane & 15);
                u32 za[8][4];
#pragma unroll
                for (int kt = 0; kt < 8; ++kt) {
                    int c = kt * 2 + hiA;
                    ldsm4(za[kt][0], za[kt][1], za[kt][2], za[kt][3],
                          smb + SM_Z + rowA * 256 + (((c ^ rowA) & 7) << 4) + ((c & 8) << 4));
                }
                float Hacc[4][4];
#pragma unroll
                for (int nt = 0; nt < 4; ++nt)
#pragma unroll
                    for (int e = 0; e < 4; ++e) Hacc[nt][e] = 0.f;
                const u32 w1b = smb + SM_WA + buf * 8192;
#pragma unroll
                for (int ktp = 0; ktp < 4; ++ktp) {
#pragma unroll
                    for (int nt = 0; nt < 4; ++nt) {
                        int jrow = nt * 8 + jr7;
                        int c = ktp * 4 + l2q;
                        u32 b0, b1, b2, b3;
                        ldsm4(b0, b1, b2, b3,
                              w1b + jrow * 256 + (((c ^ jrow) & 7) << 4) + ((c & 8) << 4));
                        mma16816(Hacc[nt], za[2 * ktp][0], za[2 * ktp][1], za[2 * ktp][2], za[2 * ktp][3], b0, b1);
                        mma16816(Hacc[nt], za[2 * ktp + 1][0], za[2 * ktp + 1][1], za[2 * ktp + 1][2], za[2 * ktp + 1][3], b2, b3);
                    }
                }
                u32 af[2][4];
#pragma unroll
                for (int kt = 0; kt < 2; ++kt) {
#pragma unroll
                    for (int e = 0; e < 4; ++e) {
                        Hacc[2 * kt][e] = fmaxf(Hacc[2 * kt][e], 0.f);
                        Hacc[2 * kt + 1][e] = fmaxf(Hacc[2 * kt + 1][e], 0.f);
                    }
                    af[kt][0] = pkbf2(Hacc[2 * kt][0], Hacc[2 * kt][1]);
                    af[kt][1] = pkbf2(Hacc[2 * kt][2], Hacc[2 * kt][3]);
                    af[kt][2] = pkbf2(Hacc[2 * kt + 1][0], Hacc[2 * kt + 1][1]);
                    af[kt][3] = pkbf2(Hacc[2 * kt + 1][2], Hacc[2 * kt + 1][3]);
                }
                gemm2_rmw(sm, smb, buf, af, fr0, fr1, jr7, l2q, gc2);
            }
        }
        __syncthreads();
        if (i < 22) load_step(sm, i + 2, t);
    }
    __syncthreads();

    // ---------- approx distances ----------
    {
        float ds = 0.f;
#pragma unroll 8
        for (int cu = 0; cu < 64; ++cu) {
            u32 v = *(u32*)(sm + SM_Z + t * 256 + ((((cu >> 2) ^ t) & 7) << 4)
                            + ((cu & 32) << 2) + (cu & 3) * 4);
            float2 zf = __bfloat1622float2(*(__nv_bfloat162*)&v);
            float e0 = zf.x + su[2 * cu], e1 = zf.y + su[2 * cu + 1];
            ds = fmaf(e0, e0, fmaf(e1, e1, ds));
        }
        s_dist[t] = ds;
        float m = ds;
#pragma unroll
        for (int o = 16; o; o >>= 1) m = fminf(m, __shfl_xor_sync(~0u, m, o));
        if (lane == 0) s_red[wid] = m;
    }
    __syncthreads();
    if (t == 0) {
        float m = s_red[0];
#pragma unroll
        for (int w = 1; w < 8; ++w) m = fminf(m, s_red[w]);
        *(float*)(sm + SM_BC) = m;
    }
    __syncthreads();
    {
        float dmin = *(float*)(sm + SM_BC);
        if (s_dist[t] <= dmin + MARGIN) {
            int pos = atomicAdd((int*)(sm + SM_CCNT), 1);
            if (pos < 16) ((int*)(sm + SM_CAND))[pos] = t;
        }
    }
    __syncthreads();

    // ---------- exact fp32 rescue ----------
    int ncand = *(int*)(sm + SM_CCNT);
    if (ncand > 16) ncand = 16;
    float* zc = (float*)(sm + SM_ZC);
    float* zb = (float*)(sm + SM_ZB);
    float* sh = (float*)(sm + SM_SH);
    u64 best = ~0ull;
    for (int c = 0; c < ncand; ++c) {
        int k = ((int*)(sm + SM_CAND))[c];
        if (t < 128) zc[t] = g_G[k * 128 + t] + g_V[b * 128 + t];
        __syncthreads();
        for (int L = 0; L < 2; ++L) {
            {
                const float* wt = g_W1t[L] + t;
                float a = 0.f;
#pragma unroll 4
                for (int d = 0; d < 128; ++d) a = fmaf(zc[d], wt[d * 256], a);
                sh[t] = fmaxf(a, 0.f);
            }
            __syncthreads();
            float upd = 0.f;
            if (t < 128) {
                const float* w2 = g_W2t + L * 32768 + t;
#pragma unroll 4
                for (int j = 0; j < 256; ++j) upd = fmaf(sh[j], w2[j * 128], upd);
            }
            __syncthreads();
            if (t < 128) zc[t] += upd;
            __syncthreads();
        }
        float p = 0.f;
        if (t < 128) { float e = zc[t] + su[t]; p = e * e; }
#pragma unroll
        for (int o = 16; o; o >>= 1) p += __shfl_xor_sync(~0u, p, o);
        if ((t & 31) == 0 && t < 128) s_red[t >> 5] = p;
        __syncthreads();
        if (t == 0)
            *(float*)(sm + SM_BC) = s_red[0] + s_red[1] + s_red[2] + s_red[3];
        __syncthreads();
        float dc = *(float*)(sm + SM_BC);
        u64 pk = ((u64)__float_as_uint(dc) << 32) | (u32)k;
        if (pk < best) {
            best = pk;
            if (t < 128) zb[t] = zc[t];
        }
        __syncthreads();
    }
    if (t == 0) out[b] = (float)(u32)(best & 0xffffffffu);
    if (t < 128) out[bs + b * 128 + t] = zb[t];
}

// ---------------- launch (exactly 3 kernels) ----------------
extern "C" void kernel_launch(void* const* d_in, const int* in_sizes, int n_in,
                              void* d_out, int out_size) {
    const float* xhat = (const float*)d_in[0];
    const float* x    = (const float*)d_in[1];
    const float* cb   = (const float*)d_in[2];
    const float* Wc   = (const float*)d_in[3];
    const float* bc   = (const float*)d_in[4];
    const float* W1_0 = (const float*)d_in[5];
    const float* W2_0 = (const float*)d_in[6];
    const float* W1_1 = (const float*)d_in[7];
    const float* W2_1 = (const float*)d_in[8];
    float* out = (float*)d_out;
    const int bs = in_sizes[0] / 128;

    static bool attr = false;
    if (!attr) {
        cudaFuncSetAttribute(k_main, cudaFuncAttributeMaxDynamicSharedMemorySize, SMEMSZ);
        attr = true;
    }

    p_weights<<<1152, 256>>>(Wc, W1_0, W1_1, W2_0, W2_1);
    p_gvpq<<<256 + bs, 256>>>(cb, bc, xhat);
    k_main<<<bs, 256, SMEMSZ>>>(xhat, x, out, bs);
}